// round 6
// baseline (speedup 1.0000x reference)
#include <cuda_runtime.h>
#include <cuda_bf16.h>
#include <math.h>

// ---------------- problem constants ----------------
#define F_IN   256
#define HEADS  8
#define HID    8
#define D1     64          // HEADS*HID
#define CLS    40
#define NEG_SLOPE 0.2f

// ---------------- scratch layout (floats) ----------------
#define NMAX        100000
#define OFF_H1      0ull                 // N*64
#define OFF_AS1     6400000ull           // N*8
#define OFF_AD1     7200000ull           // N*8
#define OFF_H2      8000000ull           // N*40
#define OFF_AS2     12000000ull          // N
#define OFF_AD2     12100000ull          // N
#define OFF_DEN1    12200000ull          // N*8   (zeroed)
#define OFF_AGG1    13000000ull          // N*64  (zeroed)
#define OFF_DEN2    19400000ull          // N     (zeroed)
#define OFF_AGG2    19500000ull          // N*40  (zeroed)
#define TOTAL_SCR   23500000ull
#define ZERO_OFF    12200000ull
#define ZERO_LEN    11300000ull

__device__ __align__(16) float g_scratch[TOTAL_SCR];

// ---------------- helpers ----------------
__device__ __forceinline__ float lrelu(float v) { return v > 0.f ? v : NEG_SLOPE * v; }

__device__ __forceinline__ void red_add_v4(float* addr, float a, float b, float c, float d) {
    asm volatile("red.global.add.v4.f32 [%0], {%1,%2,%3,%4};"
                 :: "l"(addr), "f"(a), "f"(b), "f"(c), "f"(d) : "memory");
}
__device__ __forceinline__ void red_add_f32(float* addr, float v) {
    asm volatile("red.global.add.f32 [%0], %1;" :: "l"(addr), "f"(v) : "memory");
}

// ---------------- zero scratch ----------------
__global__ void zero_kernel() {
    size_t i = (size_t)blockIdx.x * blockDim.x + threadIdx.x;
    float4* p = (float4*)(g_scratch + ZERO_OFF);
    size_t n4 = ZERO_LEN / 4;
    size_t stride = (size_t)gridDim.x * blockDim.x;
    for (; i < n4; i += stride) p[i] = make_float4(0.f, 0.f, 0.f, 0.f);
}

// ---------------- layer 1 GEMM + attention logits ----------------
// h1 = x @ W1 (N x 64); as1[n,h] = sum_c h1[n,h,c]*a_src1[h,c]; ad1 likewise.
__global__ void gemm1_kernel(const float* __restrict__ x, const float* __restrict__ W1,
                             const float* __restrict__ a_src, const float* __restrict__ a_dst,
                             int N) {
    __shared__ float Ws[64 * 64];
    __shared__ float xs[32 * 68];
    int t = threadIdx.x;
    int node0 = blockIdx.x * 32;
    int nn = t >> 3, cg = t & 7;
    int node = node0 + nn;

    float acc[8];
    #pragma unroll
    for (int i = 0; i < 8; i++) acc[i] = 0.f;

    for (int kt = 0; kt < 4; kt++) {
        __syncthreads();
        const float4* Wg4 = (const float4*)(W1 + kt * 64 * 64);
        float4* Ws4 = (float4*)Ws;
        #pragma unroll
        for (int i = 0; i < 4; i++) Ws4[t + i * 256] = Wg4[t + i * 256];
        #pragma unroll
        for (int it = 0; it < 2; it++) {
            int i = t + it * 256;
            int xn = i >> 4, c4 = i & 15;
            int nd = node0 + xn;
            float4 v = make_float4(0.f, 0.f, 0.f, 0.f);
            if (nd < N) v = ((const float4*)x)[(size_t)nd * 64 + kt * 16 + c4];
            *((float4*)(xs + xn * 68 + c4 * 4)) = v;
        }
        __syncthreads();

        const float* xr = xs + nn * 68;
        const float4* Wsv = (const float4*)Ws;
        #pragma unroll 4
        for (int k = 0; k < 64; k++) {
            float xv = xr[k];
            float4 w0 = Wsv[k * 16 + cg * 2];
            float4 w1 = Wsv[k * 16 + cg * 2 + 1];
            acc[0] += xv * w0.x; acc[1] += xv * w0.y; acc[2] += xv * w0.z; acc[3] += xv * w0.w;
            acc[4] += xv * w1.x; acc[5] += xv * w1.y; acc[6] += xv * w1.z; acc[7] += xv * w1.w;
        }
    }

    if (node < N) {
        float* h1 = g_scratch + OFF_H1 + (size_t)node * 64 + cg * 8;
        ((float4*)h1)[0] = make_float4(acc[0], acc[1], acc[2], acc[3]);
        ((float4*)h1)[1] = make_float4(acc[4], acc[5], acc[6], acc[7]);
        float as = 0.f, ad = 0.f;
        #pragma unroll
        for (int i = 0; i < 8; i++) {
            as += acc[i] * __ldg(&a_src[cg * 8 + i]);
            ad += acc[i] * __ldg(&a_dst[cg * 8 + i]);
        }
        g_scratch[OFF_AS1 + (size_t)node * 8 + cg] = as;
        g_scratch[OFF_AD1 + (size_t)node * 8 + cg] = ad;
    }
}

// ---------------- layer 1 fused edge pass ----------------
// One thread per edge. Scatter unnormalized numerator ex*h into agg1
// and ex into den1. Normalization deferred to gemm2.
__global__ void edge1_fused_kernel(const int* __restrict__ ei, int E, int Etot, int N) {
    int e = blockIdx.x * blockDim.x + threadIdx.x;
    if (e >= Etot) return;
    int s, d;
    if (e < E) { s = ei[e]; d = ei[E + e]; } else { s = d = e - E; }
    if ((unsigned)s >= (unsigned)N || (unsigned)d >= (unsigned)N) return;

    const float4* as = (const float4*)(g_scratch + OFF_AS1 + (size_t)s * 8);
    const float4* ad = (const float4*)(g_scratch + OFF_AD1 + (size_t)d * 8);
    float4 a0 = as[0], a1 = as[1], b0 = ad[0], b1 = ad[1];
    float ex[8];
    ex[0] = __expf(lrelu(a0.x + b0.x));
    ex[1] = __expf(lrelu(a0.y + b0.y));
    ex[2] = __expf(lrelu(a0.z + b0.z));
    ex[3] = __expf(lrelu(a0.w + b0.w));
    ex[4] = __expf(lrelu(a1.x + b1.x));
    ex[5] = __expf(lrelu(a1.y + b1.y));
    ex[6] = __expf(lrelu(a1.z + b1.z));
    ex[7] = __expf(lrelu(a1.w + b1.w));

    float* den = g_scratch + OFF_DEN1 + (size_t)d * 8;
    red_add_v4(den,     ex[0], ex[1], ex[2], ex[3]);
    red_add_v4(den + 4, ex[4], ex[5], ex[6], ex[7]);

    const float4* hv = (const float4*)(g_scratch + OFF_H1 + (size_t)s * 64);
    float* dst = g_scratch + OFF_AGG1 + (size_t)d * 64;
    #pragma unroll
    for (int h = 0; h < 8; h++) {
        float4 v0 = hv[h * 2], v1 = hv[h * 2 + 1];
        float w = ex[h];
        red_add_v4(dst + h * 8,     v0.x * w, v0.y * w, v0.z * w, v0.w * w);
        red_add_v4(dst + h * 8 + 4, v1.x * w, v1.y * w, v1.z * w, v1.w * w);
    }
}

// ---------------- normalize + ELU + layer 2 GEMM + logits ----------------
__global__ void gemm2_kernel(const float* __restrict__ W2, const float* __restrict__ a_src2,
                             const float* __restrict__ a_dst2, const float* __restrict__ b1,
                             int N) {
    __shared__ float Ws[64 * 40];
    __shared__ float xs[32 * 65];
    int t = threadIdx.x;
    int node0 = blockIdx.x * 32;

    for (int i = t; i < 64 * 40; i += 256) Ws[i] = W2[i];
    #pragma unroll
    for (int it = 0; it < 8; it++) {
        int i = t + it * 256;
        int nn = i >> 6, k = i & 63;
        int node = node0 + nn;
        float v = 0.f;
        if (node < N) {
            float den = g_scratch[OFF_DEN1 + (size_t)node * 8 + (k >> 3)];
            v = __fdividef(g_scratch[OFF_AGG1 + (size_t)node * 64 + k], den) + __ldg(&b1[k]);
            v = v > 0.f ? v : expm1f(v);   // ELU
        }
        xs[nn * 65 + k] = v;
    }
    __syncthreads();

    int nn = t >> 3, cg = t & 7;
    int node = node0 + nn;
    float acc[5];
    #pragma unroll
    for (int j = 0; j < 5; j++) acc[j] = 0.f;
    const float* xr = xs + nn * 65;

    #pragma unroll 4
    for (int k = 0; k < 64; k++) {
        float xv = xr[k];
        #pragma unroll
        for (int j = 0; j < 5; j++) acc[j] += xv * Ws[k * 40 + cg * 5 + j];
    }

    float pa = 0.f, pd = 0.f;
    #pragma unroll
    for (int j = 0; j < 5; j++) {
        pa += acc[j] * __ldg(&a_src2[cg * 5 + j]);
        pd += acc[j] * __ldg(&a_dst2[cg * 5 + j]);
    }
    #pragma unroll
    for (int o = 4; o >= 1; o >>= 1) {
        pa += __shfl_down_sync(0xffffffffu, pa, o, 8);
        pd += __shfl_down_sync(0xffffffffu, pd, o, 8);
    }
    if (node < N) {
        float* h2 = g_scratch + OFF_H2 + (size_t)node * 40 + cg * 5;
        #pragma unroll
        for (int j = 0; j < 5; j++) h2[j] = acc[j];
        if (cg == 0) {
            g_scratch[OFF_AS2 + node] = pa;
            g_scratch[OFF_AD2 + node] = pd;
        }
    }
}

// ---------------- layer 2 fused edge pass ----------------
// One thread per edge: RED ex to den2, ex*h2 (40 floats) to agg2.
__global__ void edge2_fused_kernel(const int* __restrict__ ei, int E, int Etot, int N) {
    int e = blockIdx.x * blockDim.x + threadIdx.x;
    if (e >= Etot) return;
    int s, d;
    if (e < E) { s = ei[e]; d = ei[E + e]; } else { s = d = e - E; }
    if ((unsigned)s >= (unsigned)N || (unsigned)d >= (unsigned)N) return;

    float ex = __expf(lrelu(g_scratch[OFF_AS2 + s] + g_scratch[OFF_AD2 + d]));
    red_add_f32(g_scratch + OFF_DEN2 + d, ex);

    const float4* hv = (const float4*)(g_scratch + OFF_H2 + (size_t)s * 40);
    float* dst = g_scratch + OFF_AGG2 + (size_t)d * 40;
    #pragma unroll
    for (int q = 0; q < 10; q++) {
        float4 v = hv[q];
        red_add_v4(dst + q * 4, v.x * ex, v.y * ex, v.z * ex, v.w * ex);
    }
}

// ---------------- final normalize + bias + log_softmax ----------------
// one warp per node, 40 classes
__global__ void finalize_kernel(const float* __restrict__ b2, float* __restrict__ out, int N) {
    int gtid = blockIdx.x * blockDim.x + threadIdx.x;
    int node = gtid >> 5;
    int lane = gtid & 31;
    if (node >= N) return;
    const float* a = g_scratch + OFF_AGG2 + (size_t)node * 40;
    float inv_den = __frcp_rn(g_scratch[OFF_DEN2 + node]);
    float v0 = a[lane] * inv_den + __ldg(&b2[lane]);
    int c2 = lane + 32;
    float v1 = (c2 < CLS) ? (a[c2] * inv_den + __ldg(&b2[c2])) : -INFINITY;
    float m = fmaxf(v0, v1);
    #pragma unroll
    for (int o = 16; o >= 1; o >>= 1) m = fmaxf(m, __shfl_xor_sync(0xffffffffu, m, o));
    float se = __expf(v0 - m) + ((c2 < CLS) ? __expf(v1 - m) : 0.f);
    #pragma unroll
    for (int o = 16; o >= 1; o >>= 1) se += __shfl_xor_sync(0xffffffffu, se, o);
    float lse = m + logf(se);
    out[(size_t)node * 40 + lane] = v0 - lse;
    if (c2 < CLS) out[(size_t)node * 40 + c2] = v1 - lse;
}

// ---------------- launch ----------------
extern "C" void kernel_launch(void* const* d_in, const int* in_sizes, int n_in,
                              void* d_out, int out_size) {
    const float* x      = (const float*)d_in[0];
    const int*   ei     = (const int*)d_in[1];     // edge_index downcast to int32 by harness
    const float* W1     = (const float*)d_in[2];
    const float* a_src1 = (const float*)d_in[3];
    const float* a_dst1 = (const float*)d_in[4];
    const float* b1     = (const float*)d_in[5];
    const float* W2     = (const float*)d_in[6];
    const float* a_src2 = (const float*)d_in[7];
    const float* a_dst2 = (const float*)d_in[8];
    const float* b2     = (const float*)d_in[9];
    float* out = (float*)d_out;

    int N = in_sizes[0] / F_IN;
    int E = in_sizes[1] / 2;
    int Etot = E + N;

    zero_kernel<<<2048, 256>>>();
    gemm1_kernel<<<(N + 31) / 32, 256>>>(x, W1, a_src1, a_dst1, N);
    edge1_fused_kernel<<<(Etot + 255) / 256, 256>>>(ei, E, Etot, N);
    gemm2_kernel<<<(N + 31) / 32, 256>>>(W2, a_src2, a_dst2, b1, N);
    edge2_fused_kernel<<<(Etot + 255) / 256, 256>>>(ei, E, Etot, N);
    finalize_kernel<<<(N * 32 + 255) / 256, 256>>>(b2, out, N);
}

// round 7
// speedup vs baseline: 1.2286x; 1.2286x over previous
#include <cuda_runtime.h>
#include <cuda_bf16.h>
#include <math.h>

// ---------------- problem constants ----------------
#define F_IN   256
#define HEADS  8
#define HID    8
#define D1     64          // HEADS*HID
#define CLS    40
#define NEG_SLOPE 0.2f

// ---------------- scratch layout (floats) ----------------
#define NMAX        100000
#define OFF_H1      0ull                 // N*64
#define OFF_AS1     6400000ull           // N*8
#define OFF_AD1     7200000ull           // N*8
#define OFF_H2      8000000ull           // N*40
#define OFF_AS2     12000000ull          // N
#define OFF_AD2     12100000ull          // N
#define OFF_DEN1    12200000ull          // N*8   (zeroed)
#define OFF_AGG1    13000000ull          // N*64  (zeroed)
#define OFF_DEN2    19400000ull          // N     (zeroed)
#define OFF_AGG2    19500000ull          // N*40  (zeroed)
#define TOTAL_SCR   23500000ull
#define ZERO_OFF    12200000ull
#define ZERO_LEN    11300000ull

__device__ __align__(16) float g_scratch[TOTAL_SCR];

// ---------------- helpers ----------------
__device__ __forceinline__ float lrelu(float v) { return v > 0.f ? v : NEG_SLOPE * v; }

__device__ __forceinline__ void red_add_v4(float* addr, float a, float b, float c, float d) {
    asm volatile("red.global.add.v4.f32 [%0], {%1,%2,%3,%4};"
                 :: "l"(addr), "f"(a), "f"(b), "f"(c), "f"(d) : "memory");
}
__device__ __forceinline__ void red_add_f32(float* addr, float v) {
    asm volatile("red.global.add.f32 [%0], %1;" :: "l"(addr), "f"(v) : "memory");
}

// ---------------- zero scratch ----------------
__global__ void zero_kernel() {
    size_t i = (size_t)blockIdx.x * blockDim.x + threadIdx.x;
    float4* p = (float4*)(g_scratch + ZERO_OFF);
    size_t n4 = ZERO_LEN / 4;
    size_t stride = (size_t)gridDim.x * blockDim.x;
    for (; i < n4; i += stride) p[i] = make_float4(0.f, 0.f, 0.f, 0.f);
}

// ---------------- layer 1 GEMM + attention logits ----------------
__global__ void gemm1_kernel(const float* __restrict__ x, const float* __restrict__ W1,
                             const float* __restrict__ a_src, const float* __restrict__ a_dst,
                             int N) {
    __shared__ float Ws[64 * 64];
    __shared__ float xs[32 * 68];
    int t = threadIdx.x;
    int node0 = blockIdx.x * 32;
    int nn = t >> 3, cg = t & 7;
    int node = node0 + nn;

    float acc[8];
    #pragma unroll
    for (int i = 0; i < 8; i++) acc[i] = 0.f;

    for (int kt = 0; kt < 4; kt++) {
        __syncthreads();
        const float4* Wg4 = (const float4*)(W1 + kt * 64 * 64);
        float4* Ws4 = (float4*)Ws;
        #pragma unroll
        for (int i = 0; i < 4; i++) Ws4[t + i * 256] = Wg4[t + i * 256];
        #pragma unroll
        for (int it = 0; it < 2; it++) {
            int i = t + it * 256;
            int xn = i >> 4, c4 = i & 15;
            int nd = node0 + xn;
            float4 v = make_float4(0.f, 0.f, 0.f, 0.f);
            if (nd < N) v = ((const float4*)x)[(size_t)nd * 64 + kt * 16 + c4];
            *((float4*)(xs + xn * 68 + c4 * 4)) = v;
        }
        __syncthreads();

        const float* xr = xs + nn * 68;
        const float4* Wsv = (const float4*)Ws;
        #pragma unroll 4
        for (int k = 0; k < 64; k++) {
            float xv = xr[k];
            float4 w0 = Wsv[k * 16 + cg * 2];
            float4 w1 = Wsv[k * 16 + cg * 2 + 1];
            acc[0] += xv * w0.x; acc[1] += xv * w0.y; acc[2] += xv * w0.z; acc[3] += xv * w0.w;
            acc[4] += xv * w1.x; acc[5] += xv * w1.y; acc[6] += xv * w1.z; acc[7] += xv * w1.w;
        }
    }

    if (node < N) {
        float* h1 = g_scratch + OFF_H1 + (size_t)node * 64 + cg * 8;
        ((float4*)h1)[0] = make_float4(acc[0], acc[1], acc[2], acc[3]);
        ((float4*)h1)[1] = make_float4(acc[4], acc[5], acc[6], acc[7]);
        float as = 0.f, ad = 0.f;
        #pragma unroll
        for (int i = 0; i < 8; i++) {
            as += acc[i] * __ldg(&a_src[cg * 8 + i]);
            ad += acc[i] * __ldg(&a_dst[cg * 8 + i]);
        }
        g_scratch[OFF_AS1 + (size_t)node * 8 + cg] = as;
        g_scratch[OFF_AD1 + (size_t)node * 8 + cg] = ad;
    }
}

// ---------------- layer 1 fused edge pass ----------------
// One thread per (edge, head): coalesced per-row access like R5's agg kernel,
// plus one scalar RED of ex into den1 (replaces the whole denom pass).
__global__ void edge1_fused_kernel(const int* __restrict__ ei, int E, int Etot, int N) {
    int idx = blockIdx.x * blockDim.x + threadIdx.x;
    if (idx >= Etot * 8) return;
    int e = idx >> 3, h = idx & 7;
    int s, d;
    if (e < E) { s = ei[e]; d = ei[E + e]; } else { s = d = e - E; }
    if ((unsigned)s >= (unsigned)N || (unsigned)d >= (unsigned)N) return;

    float lin = g_scratch[OFF_AS1 + (size_t)s * 8 + h] + g_scratch[OFF_AD1 + (size_t)d * 8 + h];
    float ex = __expf(lrelu(lin));
    red_add_f32(g_scratch + OFF_DEN1 + (size_t)d * 8 + h, ex);

    const float4* hv = (const float4*)(g_scratch + OFF_H1 + (size_t)s * 64 + h * 8);
    float4 v0 = hv[0], v1 = hv[1];
    float* dst = g_scratch + OFF_AGG1 + (size_t)d * 64 + h * 8;
    red_add_v4(dst,     v0.x * ex, v0.y * ex, v0.z * ex, v0.w * ex);
    red_add_v4(dst + 4, v1.x * ex, v1.y * ex, v1.z * ex, v1.w * ex);
}

// ---------------- normalize + ELU + layer 2 GEMM + logits ----------------
__global__ void gemm2_kernel(const float* __restrict__ W2, const float* __restrict__ a_src2,
                             const float* __restrict__ a_dst2, const float* __restrict__ b1,
                             int N) {
    __shared__ float Ws[64 * 40];
    __shared__ float xs[32 * 65];
    int t = threadIdx.x;
    int node0 = blockIdx.x * 32;

    for (int i = t; i < 64 * 40; i += 256) Ws[i] = W2[i];
    #pragma unroll
    for (int it = 0; it < 8; it++) {
        int i = t + it * 256;
        int nn = i >> 6, k = i & 63;
        int node = node0 + nn;
        float v = 0.f;
        if (node < N) {
            float den = g_scratch[OFF_DEN1 + (size_t)node * 8 + (k >> 3)];
            v = __fdividef(g_scratch[OFF_AGG1 + (size_t)node * 64 + k], den) + __ldg(&b1[k]);
            v = v > 0.f ? v : expm1f(v);   // ELU
        }
        xs[nn * 65 + k] = v;
    }
    __syncthreads();

    int nn = t >> 3, cg = t & 7;
    int node = node0 + nn;
    float acc[5];
    #pragma unroll
    for (int j = 0; j < 5; j++) acc[j] = 0.f;
    const float* xr = xs + nn * 65;

    #pragma unroll 4
    for (int k = 0; k < 64; k++) {
        float xv = xr[k];
        #pragma unroll
        for (int j = 0; j < 5; j++) acc[j] += xv * Ws[k * 40 + cg * 5 + j];
    }

    float pa = 0.f, pd = 0.f;
    #pragma unroll
    for (int j = 0; j < 5; j++) {
        pa += acc[j] * __ldg(&a_src2[cg * 5 + j]);
        pd += acc[j] * __ldg(&a_dst2[cg * 5 + j]);
    }
    #pragma unroll
    for (int o = 4; o >= 1; o >>= 1) {
        pa += __shfl_down_sync(0xffffffffu, pa, o, 8);
        pd += __shfl_down_sync(0xffffffffu, pd, o, 8);
    }
    if (node < N) {
        float* h2 = g_scratch + OFF_H2 + (size_t)node * 40 + cg * 5;
        #pragma unroll
        for (int j = 0; j < 5; j++) h2[j] = acc[j];
        if (cg == 0) {
            g_scratch[OFF_AS2 + node] = pa;
            g_scratch[OFF_AD2 + node] = pd;
        }
    }
}

// ---------------- layer 2 fused edge pass ----------------
// One thread per (edge, quad): R5 mapping; lane q==0 also REDs ex into den2.
__global__ void edge2_fused_kernel(const int* __restrict__ ei, int E, int Etot, int N) {
    int idx = blockIdx.x * blockDim.x + threadIdx.x;
    if (idx >= Etot * 10) return;
    int e = idx / 10, q = idx - e * 10;
    int s, d;
    if (e < E) { s = ei[e]; d = ei[E + e]; } else { s = d = e - E; }
    if ((unsigned)s >= (unsigned)N || (unsigned)d >= (unsigned)N) return;

    float ex = __expf(lrelu(g_scratch[OFF_AS2 + s] + g_scratch[OFF_AD2 + d]));
    if (q == 0) red_add_f32(g_scratch + OFF_DEN2 + d, ex);

    float4 v = *(const float4*)(g_scratch + OFF_H2 + (size_t)s * 40 + q * 4);
    red_add_v4(g_scratch + OFF_AGG2 + (size_t)d * 40 + q * 4,
               v.x * ex, v.y * ex, v.z * ex, v.w * ex);
}

// ---------------- final normalize + bias + log_softmax ----------------
__global__ void finalize_kernel(const float* __restrict__ b2, float* __restrict__ out, int N) {
    int gtid = blockIdx.x * blockDim.x + threadIdx.x;
    int node = gtid >> 5;
    int lane = gtid & 31;
    if (node >= N) return;
    const float* a = g_scratch + OFF_AGG2 + (size_t)node * 40;
    float inv_den = __frcp_rn(g_scratch[OFF_DEN2 + node]);
    float v0 = a[lane] * inv_den + __ldg(&b2[lane]);
    int c2 = lane + 32;
    float v1 = (c2 < CLS) ? (a[c2] * inv_den + __ldg(&b2[c2])) : -INFINITY;
    float m = fmaxf(v0, v1);
    #pragma unroll
    for (int o = 16; o >= 1; o >>= 1) m = fmaxf(m, __shfl_xor_sync(0xffffffffu, m, o));
    float se = __expf(v0 - m) + ((c2 < CLS) ? __expf(v1 - m) : 0.f);
    #pragma unroll
    for (int o = 16; o >= 1; o >>= 1) se += __shfl_xor_sync(0xffffffffu, se, o);
    float lse = m + logf(se);
    out[(size_t)node * 40 + lane] = v0 - lse;
    if (c2 < CLS) out[(size_t)node * 40 + c2] = v1 - lse;
}

// ---------------- launch ----------------
extern "C" void kernel_launch(void* const* d_in, const int* in_sizes, int n_in,
                              void* d_out, int out_size) {
    const float* x      = (const float*)d_in[0];
    const int*   ei     = (const int*)d_in[1];     // edge_index downcast to int32 by harness
    const float* W1     = (const float*)d_in[2];
    const float* a_src1 = (const float*)d_in[3];
    const float* a_dst1 = (const float*)d_in[4];
    const float* b1     = (const float*)d_in[5];
    const float* W2     = (const float*)d_in[6];
    const float* a_src2 = (const float*)d_in[7];
    const float* a_dst2 = (const float*)d_in[8];
    const float* b2     = (const float*)d_in[9];
    float* out = (float*)d_out;

    int N = in_sizes[0] / F_IN;
    int E = in_sizes[1] / 2;
    int Etot = E + N;

    zero_kernel<<<2048, 256>>>();
    gemm1_kernel<<<(N + 31) / 32, 256>>>(x, W1, a_src1, a_dst1, N);
    edge1_fused_kernel<<<(Etot * 8 + 255) / 256, 256>>>(ei, E, Etot, N);
    gemm2_kernel<<<(N + 31) / 32, 256>>>(W2, a_src2, a_dst2, b1, N);
    edge2_fused_kernel<<<(Etot * 10 + 255) / 256, 256>>>(ei, E, Etot, N);
    finalize_kernel<<<(N * 32 + 255) / 256, 256>>>(b2, out, N);
}

// round 8
// speedup vs baseline: 1.3437x; 1.0937x over previous
#include <cuda_runtime.h>
#include <cuda_bf16.h>
#include <math.h>

// ---------------- problem constants ----------------
#define F_IN   256
#define HEADS  8
#define HID    8
#define D1     64          // HEADS*HID
#define CLS    40
#define NEG_SLOPE 0.2f

// ---------------- scratch layout ----------------
#define OFF_H1      0ull                 // N*64 floats
#define OFF_AS1     6400000ull           // N*8
#define OFF_AD1     7200000ull           // N*8
#define OFF_H2      8000000ull           // N*40
#define OFF_AS2     12000000ull          // N
#define OFF_AD2     12100000ull          // N
#define OFF_AGG1    12200000ull          // N*64 (normalized, written by gather1)
// int regions (indices into (int*)g_scratch)
#define ICNT        18600000u            // N
#define IROW        18800000u            // N+1
#define ICUR        19000000u            // N
#define ICSR        19200000u            // Etot (<= 1.8M)
#define IPART       21200000u            // <= 1024
#define TOTAL_SCR   23500000ull

__device__ __align__(16) float g_scratch[TOTAL_SCR];

__device__ __forceinline__ float lrelu(float v) { return v > 0.f ? v : NEG_SLOPE * v; }

// ---------------- CSR build ----------------
__global__ void zero_int_kernel(int N) {
    int* gi = (int*)g_scratch;
    int i = blockIdx.x * blockDim.x + threadIdx.x;
    int stride = gridDim.x * blockDim.x;
    for (; i < 2 * N; i += stride) {
        if (i < N) gi[ICNT + i] = 0;
        else       gi[ICUR + (i - N)] = 0;
    }
}

__global__ void hist_kernel(const int* __restrict__ ei, int E, int Etot, int N) {
    int e = blockIdx.x * blockDim.x + threadIdx.x;
    if (e >= Etot) return;
    int d = (e < E) ? ei[E + e] : (e - E);
    if ((unsigned)d >= (unsigned)N) return;
    atomicAdd((int*)g_scratch + ICNT + d, 1);
}

// block-wise inclusive scan (Hillis-Steele), 1024 threads
__global__ void scanA_kernel(int N) {
    __shared__ int sh[1024];
    int* gi = (int*)g_scratch;
    int t = threadIdx.x, b = blockIdx.x;
    int i = b * 1024 + t;
    int v = (i < N) ? gi[ICNT + i] : 0;
    sh[t] = v;
    __syncthreads();
    for (int off = 1; off < 1024; off <<= 1) {
        int x = (t >= off) ? sh[t - off] : 0;
        __syncthreads();
        sh[t] += x;
        __syncthreads();
    }
    if (i < N) gi[IROW + i] = sh[t] - v;       // exclusive within block
    if (t == 1023) gi[IPART + b] = sh[1023];   // block total
}

__global__ void scanB_kernel(int nb) {
    __shared__ int sh[1024];
    int* gi = (int*)g_scratch;
    int t = threadIdx.x;
    int v = (t < nb) ? gi[IPART + t] : 0;
    sh[t] = v;
    __syncthreads();
    for (int off = 1; off < 1024; off <<= 1) {
        int x = (t >= off) ? sh[t - off] : 0;
        __syncthreads();
        sh[t] += x;
        __syncthreads();
    }
    if (t < nb) gi[IPART + t] = sh[t] - v;     // exclusive block offsets
}

__global__ void scanC_kernel(int N, int Etot) {
    int* gi = (int*)g_scratch;
    int i = blockIdx.x * blockDim.x + threadIdx.x;
    if (i < N) gi[IROW + i] += gi[IPART + i >> 10 ? (i >> 10) : 0];  // placeholder, fixed below
}

// (scanC re-written correctly below; the above stub is unused)
__global__ void scanC2_kernel(int N, int Etot) {
    int* gi = (int*)g_scratch;
    int i = blockIdx.x * blockDim.x + threadIdx.x;
    if (i < N) gi[IROW + i] += gi[IPART + (i >> 10)];
    if (i == 0) gi[IROW + N] = Etot;
}

__global__ void scatter_kernel(const int* __restrict__ ei, int E, int Etot, int N) {
    int e = blockIdx.x * blockDim.x + threadIdx.x;
    if (e >= Etot) return;
    int s, d;
    if (e < E) { s = ei[e]; d = ei[E + e]; } else { s = d = e - E; }
    if ((unsigned)s >= (unsigned)N || (unsigned)d >= (unsigned)N) return;
    int* gi = (int*)g_scratch;
    int pos = atomicAdd(gi + ICUR + d, 1);
    gi[ICSR + gi[IROW + d] + pos] = s;
}

// ---------------- layer 1 GEMM + attention logits ----------------
__global__ void gemm1_kernel(const float* __restrict__ x, const float* __restrict__ W1,
                             const float* __restrict__ a_src, const float* __restrict__ a_dst,
                             int N) {
    __shared__ float Ws[64 * 64];
    __shared__ float xs[32 * 68];
    int t = threadIdx.x;
    int node0 = blockIdx.x * 32;
    int nn = t >> 3, cg = t & 7;
    int node = node0 + nn;

    float acc[8];
    #pragma unroll
    for (int i = 0; i < 8; i++) acc[i] = 0.f;

    for (int kt = 0; kt < 4; kt++) {
        __syncthreads();
        const float4* Wg4 = (const float4*)(W1 + kt * 64 * 64);
        float4* Ws4 = (float4*)Ws;
        #pragma unroll
        for (int i = 0; i < 4; i++) Ws4[t + i * 256] = Wg4[t + i * 256];
        #pragma unroll
        for (int it = 0; it < 2; it++) {
            int i = t + it * 256;
            int xn = i >> 4, c4 = i & 15;
            int nd = node0 + xn;
            float4 v = make_float4(0.f, 0.f, 0.f, 0.f);
            if (nd < N) v = ((const float4*)x)[(size_t)nd * 64 + kt * 16 + c4];
            *((float4*)(xs + xn * 68 + c4 * 4)) = v;
        }
        __syncthreads();

        const float* xr = xs + nn * 68;
        const float4* Wsv = (const float4*)Ws;
        #pragma unroll 4
        for (int k = 0; k < 64; k++) {
            float xv = xr[k];
            float4 w0 = Wsv[k * 16 + cg * 2];
            float4 w1 = Wsv[k * 16 + cg * 2 + 1];
            acc[0] += xv * w0.x; acc[1] += xv * w0.y; acc[2] += xv * w0.z; acc[3] += xv * w0.w;
            acc[4] += xv * w1.x; acc[5] += xv * w1.y; acc[6] += xv * w1.z; acc[7] += xv * w1.w;
        }
    }

    if (node < N) {
        float* h1 = g_scratch + OFF_H1 + (size_t)node * 64 + cg * 8;
        ((float4*)h1)[0] = make_float4(acc[0], acc[1], acc[2], acc[3]);
        ((float4*)h1)[1] = make_float4(acc[4], acc[5], acc[6], acc[7]);
        float as = 0.f, ad = 0.f;
        #pragma unroll
        for (int i = 0; i < 8; i++) {
            as += acc[i] * __ldg(&a_src[cg * 8 + i]);
            ad += acc[i] * __ldg(&a_dst[cg * 8 + i]);
        }
        g_scratch[OFF_AS1 + (size_t)node * 8 + cg] = as;
        g_scratch[OFF_AD1 + (size_t)node * 8 + cg] = ad;
    }
}

// ---------------- layer 1 gather (warp per node) ----------------
// lane handles channels lane*2, lane*2+1 (head = lane>>2). Writes NORMALIZED agg1.
__global__ void gather1_kernel(int N) {
    int w = (blockIdx.x * blockDim.x + threadIdx.x) >> 5;
    if (w >= N) return;
    int lane = threadIdx.x & 31;
    const int* gi = (const int*)g_scratch;
    int base = gi[IROW + w];
    int deg = gi[IROW + w + 1] - base;
    float ad_h = g_scratch[OFF_AD1 + (size_t)w * 8 + (lane >> 2)];

    float accx = 0.f, accy = 0.f, den = 0.f;
    for (int i0 = 0; i0 < deg; i0 += 32) {
        int idx = i0 + lane;
        int s_l = (idx < deg) ? gi[ICSR + base + idx] : 0;
        int cnt = min(32, deg - i0);
        for (int j = 0; j < cnt; j++) {
            int s = __shfl_sync(0xffffffffu, s_l, j);
            float as = g_scratch[OFF_AS1 + (size_t)s * 8 + (lane >> 2)];
            float ex = __expf(lrelu(as + ad_h));
            float2 hv = *(const float2*)(g_scratch + OFF_H1 + (size_t)s * 64 + lane * 2);
            accx = fmaf(ex, hv.x, accx);
            accy = fmaf(ex, hv.y, accy);
            den += ex;
        }
    }
    float inv = __frcp_rn(den);
    *(float2*)(g_scratch + OFF_AGG1 + (size_t)w * 64 + lane * 2) =
        make_float2(accx * inv, accy * inv);
}

// ---------------- ELU + layer 2 GEMM + logits (agg1 already normalized) ----------------
__global__ void gemm2_kernel(const float* __restrict__ W2, const float* __restrict__ a_src2,
                             const float* __restrict__ a_dst2, const float* __restrict__ b1,
                             int N) {
    __shared__ float Ws[64 * 40];
    __shared__ float xs[32 * 65];
    int t = threadIdx.x;
    int node0 = blockIdx.x * 32;

    for (int i = t; i < 64 * 40; i += 256) Ws[i] = W2[i];
    #pragma unroll
    for (int it = 0; it < 8; it++) {
        int i = t + it * 256;
        int nn = i >> 6, k = i & 63;
        int node = node0 + nn;
        float v = 0.f;
        if (node < N) {
            v = g_scratch[OFF_AGG1 + (size_t)node * 64 + k] + __ldg(&b1[k]);
            v = v > 0.f ? v : expm1f(v);   // ELU
        }
        xs[nn * 65 + k] = v;
    }
    __syncthreads();

    int nn = t >> 3, cg = t & 7;
    int node = node0 + nn;
    float acc[5];
    #pragma unroll
    for (int j = 0; j < 5; j++) acc[j] = 0.f;
    const float* xr = xs + nn * 65;

    #pragma unroll 4
    for (int k = 0; k < 64; k++) {
        float xv = xr[k];
        #pragma unroll
        for (int j = 0; j < 5; j++) acc[j] += xv * Ws[k * 40 + cg * 5 + j];
    }

    float pa = 0.f, pd = 0.f;
    #pragma unroll
    for (int j = 0; j < 5; j++) {
        pa += acc[j] * __ldg(&a_src2[cg * 5 + j]);
        pd += acc[j] * __ldg(&a_dst2[cg * 5 + j]);
    }
    #pragma unroll
    for (int o = 4; o >= 1; o >>= 1) {
        pa += __shfl_down_sync(0xffffffffu, pa, o, 8);
        pd += __shfl_down_sync(0xffffffffu, pd, o, 8);
    }
    if (node < N) {
        float* h2 = g_scratch + OFF_H2 + (size_t)node * 40 + cg * 5;
        #pragma unroll
        for (int j = 0; j < 5; j++) h2[j] = acc[j];
        if (cg == 0) {
            g_scratch[OFF_AS2 + node] = pa;
            g_scratch[OFF_AD2 + node] = pd;
        }
    }
}

// ---------------- layer 2 gather + bias + log_softmax (warp per node) ----------------
// lane holds class lane; lanes 0-7 also hold class 32+lane.
__global__ void gather2_kernel(const float* __restrict__ b2, float* __restrict__ out, int N) {
    int w = (blockIdx.x * blockDim.x + threadIdx.x) >> 5;
    if (w >= N) return;
    int lane = threadIdx.x & 31;
    const int* gi = (const int*)g_scratch;
    int base = gi[IROW + w];
    int deg = gi[IROW + w + 1] - base;
    float ad2 = g_scratch[OFF_AD2 + w];

    float acc0 = 0.f, acc1 = 0.f, den = 0.f;
    for (int i0 = 0; i0 < deg; i0 += 32) {
        int idx = i0 + lane;
        int s_l = (idx < deg) ? gi[ICSR + base + idx] : 0;
        int cnt = min(32, deg - i0);
        for (int j = 0; j < cnt; j++) {
            int s = __shfl_sync(0xffffffffu, s_l, j);
            float as2 = g_scratch[OFF_AS2 + s];
            float ex = __expf(lrelu(as2 + ad2));
            const float* h2 = g_scratch + OFF_H2 + (size_t)s * 40;
            acc0 = fmaf(ex, h2[lane], acc0);
            if (lane < 8) acc1 = fmaf(ex, h2[32 + lane], acc1);
            den += ex;
        }
    }
    float inv = __frcp_rn(den);
    float v0 = acc0 * inv + __ldg(&b2[lane]);
    float v1 = (lane < 8) ? (acc1 * inv + __ldg(&b2[32 + lane])) : -INFINITY;

    float m = fmaxf(v0, v1);
    #pragma unroll
    for (int o = 16; o >= 1; o >>= 1) m = fmaxf(m, __shfl_xor_sync(0xffffffffu, m, o));
    float se = __expf(v0 - m) + ((lane < 8) ? __expf(v1 - m) : 0.f);
    #pragma unroll
    for (int o = 16; o >= 1; o >>= 1) se += __shfl_xor_sync(0xffffffffu, se, o);
    float lse = m + logf(se);
    out[(size_t)w * 40 + lane] = v0 - lse;
    if (lane < 8) out[(size_t)w * 40 + 32 + lane] = v1 - lse;
}

// ---------------- launch ----------------
extern "C" void kernel_launch(void* const* d_in, const int* in_sizes, int n_in,
                              void* d_out, int out_size) {
    const float* x      = (const float*)d_in[0];
    const int*   ei     = (const int*)d_in[1];
    const float* W1     = (const float*)d_in[2];
    const float* a_src1 = (const float*)d_in[3];
    const float* a_dst1 = (const float*)d_in[4];
    const float* b1     = (const float*)d_in[5];
    const float* W2     = (const float*)d_in[6];
    const float* a_src2 = (const float*)d_in[7];
    const float* a_dst2 = (const float*)d_in[8];
    const float* b2     = (const float*)d_in[9];
    float* out = (float*)d_out;

    int N = in_sizes[0] / F_IN;
    int E = in_sizes[1] / 2;
    int Etot = E + N;
    int nb = (N + 1023) / 1024;

    // CSR build (shared by both layers)
    zero_int_kernel<<<512, 256>>>(N);
    hist_kernel<<<(Etot + 255) / 256, 256>>>(ei, E, Etot, N);
    scanA_kernel<<<nb, 1024>>>(N);
    scanB_kernel<<<1, 1024>>>(nb);
    scanC2_kernel<<<(N + 255) / 256, 256>>>(N, Etot);
    scatter_kernel<<<(Etot + 255) / 256, 256>>>(ei, E, Etot, N);

    // layer 1
    gemm1_kernel<<<(N + 31) / 32, 256>>>(x, W1, a_src1, a_dst1, N);
    gather1_kernel<<<(N * 32 + 255) / 256, 256>>>(N);
    // layer 2
    gemm2_kernel<<<(N + 31) / 32, 256>>>(W2, a_src2, a_dst2, b1, N);
    gather2_kernel<<<(N * 32 + 255) / 256, 256>>>(b2, out, N);
}

// round 12
// speedup vs baseline: 2.4704x; 1.8384x over previous
#include <cuda_runtime.h>
#include <cuda_bf16.h>
#include <math.h>

// ---------------- problem constants ----------------
#define F_IN   256
#define HEADS  8
#define HID    8
#define D1     64
#define CLS    40
#define NEG_SLOPE 0.2f

// ---------------- scratch layout ----------------
#define OFF_H1      0ull                 // N*64 floats
#define OFF_AS1     6400000ull           // N*8
#define OFF_AD1     7200000ull           // N*8
#define OFF_H2      8000000ull           // N*40
#define OFF_AS2     12000000ull          // N
#define OFF_AD2     12100000ull          // N
#define OFF_AGG1    12200000ull          // N*64 (normalized, written by gather1)
// int regions (indices into (int*)g_scratch)
#define ICNT        18600000u            // N
#define IROW        18800000u            // N+1
#define ICUR        19000000u            // N
#define ICSR        19200000u            // Etot
#define IPART       21200000u            // <= 1024
#define TOTAL_SCR   23500000ull

__device__ __align__(16) float g_scratch[TOTAL_SCR];

__device__ __forceinline__ float lrelu(float v) { return v > 0.f ? v : NEG_SLOPE * v; }

// ---------------- CSR build ----------------
__global__ void zero_int_kernel(int N) {
    int* gi = (int*)g_scratch;
    int i = blockIdx.x * blockDim.x + threadIdx.x;
    int stride = gridDim.x * blockDim.x;
    for (; i < 2 * N; i += stride) {
        if (i < N) gi[ICNT + i] = 0;
        else       gi[ICUR + (i - N)] = 0;
    }
}

__global__ void hist_kernel(const int* __restrict__ ei, int E, int Etot, int N) {
    int e = blockIdx.x * blockDim.x + threadIdx.x;
    if (e >= Etot) return;
    int d = (e < E) ? ei[E + e] : (e - E);
    if ((unsigned)d >= (unsigned)N) return;
    atomicAdd((int*)g_scratch + ICNT + d, 1);
}

__global__ void scanA_kernel(int N) {
    __shared__ int sh[1024];
    int* gi = (int*)g_scratch;
    int t = threadIdx.x, b = blockIdx.x;
    int i = b * 1024 + t;
    int v = (i < N) ? gi[ICNT + i] : 0;
    sh[t] = v;
    __syncthreads();
    for (int off = 1; off < 1024; off <<= 1) {
        int x = (t >= off) ? sh[t - off] : 0;
        __syncthreads();
        sh[t] += x;
        __syncthreads();
    }
    if (i < N) gi[IROW + i] = sh[t] - v;
    if (t == 1023) gi[IPART + b] = sh[1023];
}

__global__ void scanB_kernel(int nb) {
    __shared__ int sh[1024];
    int* gi = (int*)g_scratch;
    int t = threadIdx.x;
    int v = (t < nb) ? gi[IPART + t] : 0;
    sh[t] = v;
    __syncthreads();
    for (int off = 1; off < 1024; off <<= 1) {
        int x = (t >= off) ? sh[t - off] : 0;
        __syncthreads();
        sh[t] += x;
        __syncthreads();
    }
    if (t < nb) gi[IPART + t] = sh[t] - v;
}

__global__ void scanC_kernel(int N, int Etot) {
    int* gi = (int*)g_scratch;
    int i = blockIdx.x * blockDim.x + threadIdx.x;
    if (i < N) gi[IROW + i] += gi[IPART + (i >> 10)];
    if (i == 0) gi[IROW + N] = Etot;
}

__global__ void scatter_kernel(const int* __restrict__ ei, int E, int Etot, int N) {
    int e = blockIdx.x * blockDim.x + threadIdx.x;
    if (e >= Etot) return;
    int s, d;
    if (e < E) { s = ei[e]; d = ei[E + e]; } else { s = d = e - E; }
    if ((unsigned)s >= (unsigned)N || (unsigned)d >= (unsigned)N) return;
    int* gi = (int*)g_scratch;
    int pos = atomicAdd(gi + ICUR + d, 1);
    gi[ICSR + gi[IROW + d] + pos] = s;
}

// ---------------- layer 1 GEMM (register tiled) + attention logits ----------------
// Tile: 256 nodes x 64 outs. 256 threads: r=t>>3 (8-node group), c=t&7 (head).
__global__ void gemm1_kernel(const float* __restrict__ x, const float* __restrict__ W1,
                             const float* __restrict__ a_src, const float* __restrict__ a_dst,
                             int N) {
    __shared__ __align__(16) float xs[256 * 33];
    __shared__ __align__(16) float Ws[32 * 68];
    int t = threadIdx.x;
    int node0 = blockIdx.x * 256;
    int r = t >> 3, c = t & 7;

    float acc[8][8];
    #pragma unroll
    for (int i = 0; i < 8; i++)
        #pragma unroll
        for (int j = 0; j < 8; j++) acc[i][j] = 0.f;

    for (int kt = 0; kt < 8; kt++) {
        __syncthreads();
        #pragma unroll
        for (int p = 0; p < 8; p++) {
            int i = t + p * 256;
            int nl = i >> 3, q = i & 7;
            int nd = node0 + nl;
            float4 v = make_float4(0.f, 0.f, 0.f, 0.f);
            if (nd < N) v = ((const float4*)x)[(size_t)nd * 64 + kt * 8 + q];
            float* dp = &xs[nl * 33 + q * 4];
            dp[0] = v.x; dp[1] = v.y; dp[2] = v.z; dp[3] = v.w;
        }
        #pragma unroll
        for (int p = 0; p < 2; p++) {
            int i = t + p * 256;
            int k = i >> 4, o4 = i & 15;
            float4 v = ((const float4*)W1)[(size_t)(kt * 32 + k) * 16 + o4];
            float* dp = &Ws[k * 68 + o4 * 4];
            dp[0] = v.x; dp[1] = v.y; dp[2] = v.z; dp[3] = v.w;
        }
        __syncthreads();

        #pragma unroll 4
        for (int kk = 0; kk < 32; kk++) {
            float wv[8];
            *(float4*)wv       = *(const float4*)&Ws[kk * 68 + c * 8];
            *(float4*)(wv + 4) = *(const float4*)&Ws[kk * 68 + c * 8 + 4];
            float xv[8];
            #pragma unroll
            for (int i = 0; i < 8; i++) xv[i] = xs[(r * 8 + i) * 33 + kk];
            #pragma unroll
            for (int i = 0; i < 8; i++)
                #pragma unroll
                for (int j = 0; j < 8; j++) acc[i][j] = fmaf(xv[i], wv[j], acc[i][j]);
        }
    }

    float asw[8], adw[8];
    #pragma unroll
    for (int j = 0; j < 8; j++) {
        asw[j] = __ldg(&a_src[c * 8 + j]);
        adw[j] = __ldg(&a_dst[c * 8 + j]);
    }
    #pragma unroll
    for (int i = 0; i < 8; i++) {
        int node = node0 + r * 8 + i;
        if (node < N) {
            float* h1 = g_scratch + OFF_H1 + (size_t)node * 64 + c * 8;
            ((float4*)h1)[0] = make_float4(acc[i][0], acc[i][1], acc[i][2], acc[i][3]);
            ((float4*)h1)[1] = make_float4(acc[i][4], acc[i][5], acc[i][6], acc[i][7]);
            float as = 0.f, ad = 0.f;
            #pragma unroll
            for (int j = 0; j < 8; j++) {
                as = fmaf(acc[i][j], asw[j], as);
                ad = fmaf(acc[i][j], adw[j], ad);
            }
            g_scratch[OFF_AS1 + (size_t)node * 8 + c] = as;
            g_scratch[OFF_AD1 + (size_t)node * 8 + c] = ad;
        }
    }
}

// ---------------- layer 1 gather (R8 verbatim: warp per node) ----------------
// lane handles channels lane*2, lane*2+1 (head = lane>>2). Writes NORMALIZED agg1.
__global__ void gather1_kernel(int N) {
    int w = (blockIdx.x * blockDim.x + threadIdx.x) >> 5;
    if (w >= N) return;
    int lane = threadIdx.x & 31;
    const int* gi = (const int*)g_scratch;
    int base = gi[IROW + w];
    int deg = gi[IROW + w + 1] - base;
    float ad_h = g_scratch[OFF_AD1 + (size_t)w * 8 + (lane >> 2)];

    float accx = 0.f, accy = 0.f, den = 0.f;
    for (int i0 = 0; i0 < deg; i0 += 32) {
        int idx = i0 + lane;
        int s_l = (idx < deg) ? gi[ICSR + base + idx] : 0;
        int cnt = min(32, deg - i0);
        for (int j = 0; j < cnt; j++) {
            int s = __shfl_sync(0xffffffffu, s_l, j);
            float as = g_scratch[OFF_AS1 + (size_t)s * 8 + (lane >> 2)];
            float ex = __expf(lrelu(as + ad_h));
            float2 hv = *(const float2*)(g_scratch + OFF_H1 + (size_t)s * 64 + lane * 2);
            accx = fmaf(ex, hv.x, accx);
            accy = fmaf(ex, hv.y, accy);
            den += ex;
        }
    }
    float inv = __frcp_rn(den);
    *(float2*)(g_scratch + OFF_AGG1 + (size_t)w * 64 + lane * 2) =
        make_float2(accx * inv, accy * inv);
}

// ---------------- ELU + layer 2 GEMM (register tiled) + logits ----------------
// Tile: 256 nodes x 40 outs. 256 threads: r=t>>3, c=t&7 (classes c*5..c*5+4).
__global__ void gemm2_kernel(const float* __restrict__ W2, const float* __restrict__ a_src2,
                             const float* __restrict__ a_dst2, const float* __restrict__ b1,
                             int N) {
    __shared__ __align__(16) float xs[256 * 33];
    __shared__ __align__(16) float Ws[32 * 44];
    int t = threadIdx.x;
    int node0 = blockIdx.x * 256;
    int r = t >> 3, c = t & 7;

    float acc[8][5];
    #pragma unroll
    for (int i = 0; i < 8; i++)
        #pragma unroll
        for (int j = 0; j < 5; j++) acc[i][j] = 0.f;

    for (int kt = 0; kt < 2; kt++) {
        __syncthreads();
        #pragma unroll
        for (int p = 0; p < 8; p++) {
            int i = t + p * 256;
            int nl = i >> 3, q = i & 7;
            int nd = node0 + nl;
            float4 v = make_float4(0.f, 0.f, 0.f, 0.f);
            if (nd < N) {
                v = *(const float4*)(g_scratch + OFF_AGG1 + (size_t)nd * 64 + kt * 32 + q * 4);
                float4 bv = *(const float4*)&b1[kt * 32 + q * 4];
                v.x += bv.x; v.y += bv.y; v.z += bv.z; v.w += bv.w;
                v.x = v.x > 0.f ? v.x : expm1f(v.x);
                v.y = v.y > 0.f ? v.y : expm1f(v.y);
                v.z = v.z > 0.f ? v.z : expm1f(v.z);
                v.w = v.w > 0.f ? v.w : expm1f(v.w);
            }
            float* dp = &xs[nl * 33 + q * 4];
            dp[0] = v.x; dp[1] = v.y; dp[2] = v.z; dp[3] = v.w;
        }
        // W chunk: 32 rows x 40 cols = 320 float4 — loop to cover all with 256 threads
        for (int i = t; i < 320; i += 256) {
            int k = i / 10, o4 = i % 10;
            float4 v = ((const float4*)W2)[(size_t)(kt * 32 + k) * 10 + o4];
            float* dp = &Ws[k * 44 + o4 * 4];
            dp[0] = v.x; dp[1] = v.y; dp[2] = v.z; dp[3] = v.w;
        }
        __syncthreads();

        #pragma unroll 4
        for (int kk = 0; kk < 32; kk++) {
            float wv[5];
            #pragma unroll
            for (int j = 0; j < 5; j++) wv[j] = Ws[kk * 44 + c * 5 + j];
            float xv[8];
            #pragma unroll
            for (int i = 0; i < 8; i++) xv[i] = xs[(r * 8 + i) * 33 + kk];
            #pragma unroll
            for (int i = 0; i < 8; i++)
                #pragma unroll
                for (int j = 0; j < 5; j++) acc[i][j] = fmaf(xv[i], wv[j], acc[i][j]);
        }
    }

    float a2s[5], a2d[5];
    #pragma unroll
    for (int j = 0; j < 5; j++) {
        a2s[j] = __ldg(&a_src2[c * 5 + j]);
        a2d[j] = __ldg(&a_dst2[c * 5 + j]);
    }
    #pragma unroll
    for (int i = 0; i < 8; i++) {
        int node = node0 + r * 8 + i;
        float pa = 0.f, pd = 0.f;
        #pragma unroll
        for (int j = 0; j < 5; j++) {
            pa = fmaf(acc[i][j], a2s[j], pa);
            pd = fmaf(acc[i][j], a2d[j], pd);
        }
        #pragma unroll
        for (int o = 4; o >= 1; o >>= 1) {
            pa += __shfl_down_sync(0xffffffffu, pa, o, 8);
            pd += __shfl_down_sync(0xffffffffu, pd, o, 8);
        }
        if (node < N) {
            float* h2 = g_scratch + OFF_H2 + (size_t)node * 40 + c * 5;
            #pragma unroll
            for (int j = 0; j < 5; j++) h2[j] = acc[i][j];
            if (c == 0) {
                g_scratch[OFF_AS2 + node] = pa;
                g_scratch[OFF_AD2 + node] = pd;
            }
        }
    }
}

// ---------------- layer 2 gather + bias + log_softmax (R8 verbatim) ----------------
// lane holds class lane; lanes 0-7 also hold class 32+lane.
__global__ void gather2_kernel(const float* __restrict__ b2, float* __restrict__ out, int N) {
    int w = (blockIdx.x * blockDim.x + threadIdx.x) >> 5;
    if (w >= N) return;
    int lane = threadIdx.x & 31;
    const int* gi = (const int*)g_scratch;
    int base = gi[IROW + w];
    int deg = gi[IROW + w + 1] - base;
    float ad2 = g_scratch[OFF_AD2 + w];

    float acc0 = 0.f, acc1 = 0.f, den = 0.f;
    for (int i0 = 0; i0 < deg; i0 += 32) {
        int idx = i0 + lane;
        int s_l = (idx < deg) ? gi[ICSR + base + idx] : 0;
        int cnt = min(32, deg - i0);
        for (int j = 0; j < cnt; j++) {
            int s = __shfl_sync(0xffffffffu, s_l, j);
            float as2 = g_scratch[OFF_AS2 + s];
            float ex = __expf(lrelu(as2 + ad2));
            const float* h2 = g_scratch + OFF_H2 + (size_t)s * 40;
            acc0 = fmaf(ex, h2[lane], acc0);
            if (lane < 8) acc1 = fmaf(ex, h2[32 + lane], acc1);
            den += ex;
        }
    }
    float inv = __frcp_rn(den);
    float v0 = acc0 * inv + __ldg(&b2[lane]);
    float v1 = (lane < 8) ? (acc1 * inv + __ldg(&b2[32 + lane])) : -INFINITY;

    float m = fmaxf(v0, v1);
    #pragma unroll
    for (int o = 16; o >= 1; o >>= 1) m = fmaxf(m, __shfl_xor_sync(0xffffffffu, m, o));
    float se = __expf(v0 - m) + ((lane < 8) ? __expf(v1 - m) : 0.f);
    #pragma unroll
    for (int o = 16; o >= 1; o >>= 1) se += __shfl_xor_sync(0xffffffffu, se, o);
    float lse = m + logf(se);
    out[(size_t)w * 40 + lane] = v0 - lse;
    if (lane < 8) out[(size_t)w * 40 + 32 + lane] = v1 - lse;
}

// ---------------- launch ----------------
extern "C" void kernel_launch(void* const* d_in, const int* in_sizes, int n_in,
                              void* d_out, int out_size) {
    const float* x      = (const float*)d_in[0];
    const int*   ei     = (const int*)d_in[1];
    const float* W1     = (const float*)d_in[2];
    const float* a_src1 = (const float*)d_in[3];
    const float* a_dst1 = (const float*)d_in[4];
    const float* b1     = (const float*)d_in[5];
    const float* W2     = (const float*)d_in[6];
    const float* a_src2 = (const float*)d_in[7];
    const float* a_dst2 = (const float*)d_in[8];
    const float* b2     = (const float*)d_in[9];
    float* out = (float*)d_out;

    int N = in_sizes[0] / F_IN;
    int E = in_sizes[1] / 2;
    int Etot = E + N;
    int nb = (N + 1023) / 1024;

    // CSR build (shared by both layers)
    zero_int_kernel<<<512, 256>>>(N);
    hist_kernel<<<(Etot + 255) / 256, 256>>>(ei, E, Etot, N);
    scanA_kernel<<<nb, 1024>>>(N);
    scanB_kernel<<<1, 1024>>>(nb);
    scanC_kernel<<<(N + 255) / 256, 256>>>(N, Etot);
    scatter_kernel<<<(Etot + 255) / 256, 256>>>(ei, E, Etot, N);

    // layer 1
    gemm1_kernel<<<(N + 255) / 256, 256>>>(x, W1, a_src1, a_dst1, N);
    gather1_kernel<<<(N * 32 + 255) / 256, 256>>>(N);
    // layer 2
    gemm2_kernel<<<(N + 255) / 256, 256>>>(W2, a_src2, a_dst2, b1, N);
    gather2_kernel<<<(N * 32 + 255) / 256, 256>>>(b2, out, N);
}

// round 15
// speedup vs baseline: 2.7383x; 1.1085x over previous
#include <cuda_runtime.h>
#include <cuda_bf16.h>
#include <math.h>

// ---------------- problem constants ----------------
#define F_IN   256
#define HEADS  8
#define HID    8
#define D1     64
#define CLS    40
#define NEG_SLOPE 0.2f

// ---------------- scratch layout ----------------
#define OFF_H1      0ull                 // N*64 floats
#define OFF_AS1     6400000ull           // N*8
#define OFF_AD1     7200000ull           // N*8
#define OFF_H2      8000000ull           // N*40
#define OFF_AS2     12000000ull          // N
#define OFF_AD2     12100000ull          // N
#define OFF_AGG1    12200000ull          // N*64 (normalized, written by gather1)
// int regions (indices into (int*)g_scratch)
#define ICNT        18600000u            // N
#define IROW        18800000u            // N+1
#define ICUR        19000000u            // N
#define ICSR        19200000u            // Etot
#define IPART       21200000u            // <= 1024
#define TOTAL_SCR   23500000ull

__device__ __align__(16) float g_scratch[TOTAL_SCR];

__device__ __forceinline__ float lrelu(float v) { return v > 0.f ? v : NEG_SLOPE * v; }

// ---------------- CSR build ----------------
__global__ void zero_int_kernel(int N) {
    int* gi = (int*)g_scratch;
    int i = blockIdx.x * blockDim.x + threadIdx.x;
    int stride = gridDim.x * blockDim.x;
    for (; i < 2 * N; i += stride) {
        if (i < N) gi[ICNT + i] = 0;
        else       gi[ICUR + (i - N)] = 0;
    }
}

__global__ void hist_kernel(const int* __restrict__ ei, int E, int Etot, int N) {
    int e = blockIdx.x * blockDim.x + threadIdx.x;
    if (e >= Etot) return;
    int d = (e < E) ? ei[E + e] : (e - E);
    if ((unsigned)d >= (unsigned)N) return;
    atomicAdd((int*)g_scratch + ICNT + d, 1);
}

__global__ void scanA_kernel(int N) {
    __shared__ int sh[1024];
    int* gi = (int*)g_scratch;
    int t = threadIdx.x, b = blockIdx.x;
    int i = b * 1024 + t;
    int v = (i < N) ? gi[ICNT + i] : 0;
    sh[t] = v;
    __syncthreads();
    for (int off = 1; off < 1024; off <<= 1) {
        int x = (t >= off) ? sh[t - off] : 0;
        __syncthreads();
        sh[t] += x;
        __syncthreads();
    }
    if (i < N) gi[IROW + i] = sh[t] - v;
    if (t == 1023) gi[IPART + b] = sh[1023];
}

__global__ void scanB_kernel(int nb) {
    __shared__ int sh[1024];
    int* gi = (int*)g_scratch;
    int t = threadIdx.x;
    int v = (t < nb) ? gi[IPART + t] : 0;
    sh[t] = v;
    __syncthreads();
    for (int off = 1; off < 1024; off <<= 1) {
        int x = (t >= off) ? sh[t - off] : 0;
        __syncthreads();
        sh[t] += x;
        __syncthreads();
    }
    if (t < nb) gi[IPART + t] = sh[t] - v;
}

__global__ void scanC_kernel(int N, int Etot) {
    int* gi = (int*)g_scratch;
    int i = blockIdx.x * blockDim.x + threadIdx.x;
    if (i < N) gi[IROW + i] += gi[IPART + (i >> 10)];
    if (i == 0) gi[IROW + N] = Etot;
}

__global__ void scatter_kernel(const int* __restrict__ ei, int E, int Etot, int N) {
    int e = blockIdx.x * blockDim.x + threadIdx.x;
    if (e >= Etot) return;
    int s, d;
    if (e < E) { s = ei[e]; d = ei[E + e]; } else { s = d = e - E; }
    if ((unsigned)s >= (unsigned)N || (unsigned)d >= (unsigned)N) return;
    int* gi = (int*)g_scratch;
    int pos = atomicAdd(gi + ICUR + d, 1);
    gi[ICSR + gi[IROW + d] + pos] = s;
}

// ---------------- layer 1 GEMM (register tiled) + attention logits ----------------
// Tile: 256 nodes x 64 outs. 256 threads: r=t>>3 (8-node group), c=t&7 (head).
__global__ void gemm1_kernel(const float* __restrict__ x, const float* __restrict__ W1,
                             const float* __restrict__ a_src, const float* __restrict__ a_dst,
                             int N) {
    __shared__ __align__(16) float xs[256 * 33];
    __shared__ __align__(16) float Ws[32 * 68];
    int t = threadIdx.x;
    int node0 = blockIdx.x * 256;
    int r = t >> 3, c = t & 7;

    float acc[8][8];
    #pragma unroll
    for (int i = 0; i < 8; i++)
        #pragma unroll
        for (int j = 0; j < 8; j++) acc[i][j] = 0.f;

    for (int kt = 0; kt < 8; kt++) {
        __syncthreads();
        #pragma unroll
        for (int p = 0; p < 8; p++) {
            int i = t + p * 256;
            int nl = i >> 3, q = i & 7;
            int nd = node0 + nl;
            float4 v = make_float4(0.f, 0.f, 0.f, 0.f);
            if (nd < N) v = ((const float4*)x)[(size_t)nd * 64 + kt * 8 + q];
            float* dp = &xs[nl * 33 + q * 4];
            dp[0] = v.x; dp[1] = v.y; dp[2] = v.z; dp[3] = v.w;
        }
        #pragma unroll
        for (int p = 0; p < 2; p++) {
            int i = t + p * 256;
            int k = i >> 4, o4 = i & 15;
            float4 v = ((const float4*)W1)[(size_t)(kt * 32 + k) * 16 + o4];
            float* dp = &Ws[k * 68 + o4 * 4];
            dp[0] = v.x; dp[1] = v.y; dp[2] = v.z; dp[3] = v.w;
        }
        __syncthreads();

        #pragma unroll 4
        for (int kk = 0; kk < 32; kk++) {
            float wv[8];
            *(float4*)wv       = *(const float4*)&Ws[kk * 68 + c * 8];
            *(float4*)(wv + 4) = *(const float4*)&Ws[kk * 68 + c * 8 + 4];
            float xv[8];
            #pragma unroll
            for (int i = 0; i < 8; i++) xv[i] = xs[(r * 8 + i) * 33 + kk];
            #pragma unroll
            for (int i = 0; i < 8; i++)
                #pragma unroll
                for (int j = 0; j < 8; j++) acc[i][j] = fmaf(xv[i], wv[j], acc[i][j]);
        }
    }

    float asw[8], adw[8];
    #pragma unroll
    for (int j = 0; j < 8; j++) {
        asw[j] = __ldg(&a_src[c * 8 + j]);
        adw[j] = __ldg(&a_dst[c * 8 + j]);
    }
    #pragma unroll
    for (int i = 0; i < 8; i++) {
        int node = node0 + r * 8 + i;
        if (node < N) {
            float* h1 = g_scratch + OFF_H1 + (size_t)node * 64 + c * 8;
            ((float4*)h1)[0] = make_float4(acc[i][0], acc[i][1], acc[i][2], acc[i][3]);
            ((float4*)h1)[1] = make_float4(acc[i][4], acc[i][5], acc[i][6], acc[i][7]);
            float as = 0.f, ad = 0.f;
            #pragma unroll
            for (int j = 0; j < 8; j++) {
                as = fmaf(acc[i][j], asw[j], as);
                ad = fmaf(acc[i][j], adw[j], ad);
            }
            g_scratch[OFF_AS1 + (size_t)node * 8 + c] = as;
            g_scratch[OFF_AD1 + (size_t)node * 8 + c] = ad;
        }
    }
}

// ---------------- layer 1 gather: warp per node, 4 edge-slots x 8 lanes ----------------
// lane l = lane&7 owns head l (channels l*8..l*8+7); slot = lane>>3 owns edge i0+slot.
__global__ void gather1_kernel(int N) {
    int w = (blockIdx.x * blockDim.x + threadIdx.x) >> 5;
    if (w >= N) return;
    int lane = threadIdx.x & 31;
    int l = lane & 7, slot = lane >> 3;
    const int* gi = (const int*)g_scratch;
    int base = gi[IROW + w];
    int deg = gi[IROW + w + 1] - base;
    float ad = g_scratch[OFF_AD1 + (size_t)w * 8 + l];

    float acc[8];
    #pragma unroll
    for (int j = 0; j < 8; j++) acc[j] = 0.f;
    float den = 0.f;

    for (int i0 = 0; i0 < deg; i0 += 4) {
        int idx = i0 + slot;
        bool valid = idx < deg;
        int s = valid ? gi[ICSR + base + idx] : w;
        float as = g_scratch[OFF_AS1 + (size_t)s * 8 + l];
        float ex = valid ? __expf(lrelu(as + ad)) : 0.f;
        const float4* hv = (const float4*)(g_scratch + OFF_H1 + (size_t)s * 64 + l * 8);
        float4 v0 = hv[0], v1 = hv[1];
        acc[0] = fmaf(ex, v0.x, acc[0]); acc[1] = fmaf(ex, v0.y, acc[1]);
        acc[2] = fmaf(ex, v0.z, acc[2]); acc[3] = fmaf(ex, v0.w, acc[3]);
        acc[4] = fmaf(ex, v1.x, acc[4]); acc[5] = fmaf(ex, v1.y, acc[5]);
        acc[6] = fmaf(ex, v1.z, acc[6]); acc[7] = fmaf(ex, v1.w, acc[7]);
        den += ex;
    }
    // reduce across 4 slots (xor over bits 3,4 of lane)
    #pragma unroll
    for (int m = 8; m <= 16; m <<= 1) {
        den += __shfl_xor_sync(0xffffffffu, den, m);
        #pragma unroll
        for (int j = 0; j < 8; j++) acc[j] += __shfl_xor_sync(0xffffffffu, acc[j], m);
    }
    if (slot == 0) {
        float inv = __frcp_rn(den);
        float* dst = g_scratch + OFF_AGG1 + (size_t)w * 64 + l * 8;
        ((float4*)dst)[0] = make_float4(acc[0] * inv, acc[1] * inv, acc[2] * inv, acc[3] * inv);
        ((float4*)dst)[1] = make_float4(acc[4] * inv, acc[5] * inv, acc[6] * inv, acc[7] * inv);
    }
}

// ---------------- ELU + layer 2 GEMM (register tiled) + logits ----------------
// Tile: 256 nodes x 40 outs. 256 threads: r=t>>3, c=t&7 (classes c*5..c*5+4).
__global__ void gemm2_kernel(const float* __restrict__ W2, const float* __restrict__ a_src2,
                             const float* __restrict__ a_dst2, const float* __restrict__ b1,
                             int N) {
    __shared__ __align__(16) float xs[256 * 33];
    __shared__ __align__(16) float Ws[32 * 44];
    int t = threadIdx.x;
    int node0 = blockIdx.x * 256;
    int r = t >> 3, c = t & 7;

    float acc[8][5];
    #pragma unroll
    for (int i = 0; i < 8; i++)
        #pragma unroll
        for (int j = 0; j < 5; j++) acc[i][j] = 0.f;

    for (int kt = 0; kt < 2; kt++) {
        __syncthreads();
        #pragma unroll
        for (int p = 0; p < 8; p++) {
            int i = t + p * 256;
            int nl = i >> 3, q = i & 7;
            int nd = node0 + nl;
            float4 v = make_float4(0.f, 0.f, 0.f, 0.f);
            if (nd < N) {
                v = *(const float4*)(g_scratch + OFF_AGG1 + (size_t)nd * 64 + kt * 32 + q * 4);
                float4 bv = *(const float4*)&b1[kt * 32 + q * 4];
                v.x += bv.x; v.y += bv.y; v.z += bv.z; v.w += bv.w;
                v.x = v.x > 0.f ? v.x : expm1f(v.x);
                v.y = v.y > 0.f ? v.y : expm1f(v.y);
                v.z = v.z > 0.f ? v.z : expm1f(v.z);
                v.w = v.w > 0.f ? v.w : expm1f(v.w);
            }
            float* dp = &xs[nl * 33 + q * 4];
            dp[0] = v.x; dp[1] = v.y; dp[2] = v.z; dp[3] = v.w;
        }
        // W chunk: 32 rows x 40 cols = 320 float4 — loop to cover all with 256 threads
        for (int i = t; i < 320; i += 256) {
            int k = i / 10, o4 = i % 10;
            float4 v = ((const float4*)W2)[(size_t)(kt * 32 + k) * 10 + o4];
            float* dp = &Ws[k * 44 + o4 * 4];
            dp[0] = v.x; dp[1] = v.y; dp[2] = v.z; dp[3] = v.w;
        }
        __syncthreads();

        #pragma unroll 4
        for (int kk = 0; kk < 32; kk++) {
            float wv[5];
            #pragma unroll
            for (int j = 0; j < 5; j++) wv[j] = Ws[kk * 44 + c * 5 + j];
            float xv[8];
            #pragma unroll
            for (int i = 0; i < 8; i++) xv[i] = xs[(r * 8 + i) * 33 + kk];
            #pragma unroll
            for (int i = 0; i < 8; i++)
                #pragma unroll
                for (int j = 0; j < 5; j++) acc[i][j] = fmaf(xv[i], wv[j], acc[i][j]);
        }
    }

    float a2s[5], a2d[5];
    #pragma unroll
    for (int j = 0; j < 5; j++) {
        a2s[j] = __ldg(&a_src2[c * 5 + j]);
        a2d[j] = __ldg(&a_dst2[c * 5 + j]);
    }
    #pragma unroll
    for (int i = 0; i < 8; i++) {
        int node = node0 + r * 8 + i;
        float pa = 0.f, pd = 0.f;
        #pragma unroll
        for (int j = 0; j < 5; j++) {
            pa = fmaf(acc[i][j], a2s[j], pa);
            pd = fmaf(acc[i][j], a2d[j], pd);
        }
        #pragma unroll
        for (int o = 4; o >= 1; o >>= 1) {
            pa += __shfl_down_sync(0xffffffffu, pa, o, 8);
            pd += __shfl_down_sync(0xffffffffu, pd, o, 8);
        }
        if (node < N) {
            float* h2 = g_scratch + OFF_H2 + (size_t)node * 40 + c * 5;
            #pragma unroll
            for (int j = 0; j < 5; j++) h2[j] = acc[i][j];
            if (c == 0) {
                g_scratch[OFF_AS2 + node] = pa;
                g_scratch[OFF_AD2 + node] = pd;
            }
        }
    }
}

// ---------------- layer 2 gather + bias + log_softmax: 4 slots x 8 lanes ----------------
// lane l holds classes {l, l+8, l+16, l+24, l+32}; slot owns edge i0+slot.
__global__ void gather2_kernel(const float* __restrict__ b2, float* __restrict__ out, int N) {
    int w = (blockIdx.x * blockDim.x + threadIdx.x) >> 5;
    if (w >= N) return;
    int lane = threadIdx.x & 31;
    int l = lane & 7, slot = lane >> 3;
    const int* gi = (const int*)g_scratch;
    int base = gi[IROW + w];
    int deg = gi[IROW + w + 1] - base;
    float ad2 = g_scratch[OFF_AD2 + w];

    float acc[5];
    #pragma unroll
    for (int j = 0; j < 5; j++) acc[j] = 0.f;
    float den = 0.f;

    for (int i0 = 0; i0 < deg; i0 += 4) {
        int idx = i0 + slot;
        bool valid = idx < deg;
        int s = valid ? gi[ICSR + base + idx] : w;
        float as2 = g_scratch[OFF_AS2 + s];
        float ex = valid ? __expf(lrelu(as2 + ad2)) : 0.f;
        const float* h2 = g_scratch + OFF_H2 + (size_t)s * 40;
        #pragma unroll
        for (int j = 0; j < 5; j++) acc[j] = fmaf(ex, h2[l + 8 * j], acc[j]);
        den += ex;
    }
    #pragma unroll
    for (int m = 8; m <= 16; m <<= 1) {
        den += __shfl_xor_sync(0xffffffffu, den, m);
        #pragma unroll
        for (int j = 0; j < 5; j++) acc[j] += __shfl_xor_sync(0xffffffffu, acc[j], m);
    }
    float inv = __frcp_rn(den);
    float v[5];
    #pragma unroll
    for (int j = 0; j < 5; j++) v[j] = acc[j] * inv + __ldg(&b2[l + 8 * j]);

    // log_softmax over 40 values spread across 8 lanes x 5 regs (replicated in slots)
    float m0 = v[0];
    #pragma unroll
    for (int j = 1; j < 5; j++) m0 = fmaxf(m0, v[j]);
    #pragma unroll
    for (int o = 1; o <= 4; o <<= 1) m0 = fmaxf(m0, __shfl_xor_sync(0xffffffffu, m0, o));
    float se = 0.f;
    #pragma unroll
    for (int j = 0; j < 5; j++) se += __expf(v[j] - m0);
    #pragma unroll
    for (int o = 1; o <= 4; o <<= 1) se += __shfl_xor_sync(0xffffffffu, se, o);
    float lse = m0 + logf(se);
    if (slot == 0) {
        #pragma unroll
        for (int j = 0; j < 5; j++) out[(size_t)w * 40 + l + 8 * j] = v[j] - lse;
    }
}

// ---------------- launch ----------------
extern "C" void kernel_launch(void* const* d_in, const int* in_sizes, int n_in,
                              void* d_out, int out_size) {
    const float* x      = (const float*)d_in[0];
    const int*   ei     = (const int*)d_in[1];
    const float* W1     = (const float*)d_in[2];
    const float* a_src1 = (const float*)d_in[3];
    const float* a_dst1 = (const float*)d_in[4];
    const float* b1     = (const float*)d_in[5];
    const float* W2     = (const float*)d_in[6];
    const float* a_src2 = (const float*)d_in[7];
    const float* a_dst2 = (const float*)d_in[8];
    const float* b2     = (const float*)d_in[9];
    float* out = (float*)d_out;

    int N = in_sizes[0] / F_IN;
    int E = in_sizes[1] / 2;
    int Etot = E + N;
    int nb = (N + 1023) / 1024;

    // CSR build (shared by both layers)
    zero_int_kernel<<<512, 256>>>(N);
    hist_kernel<<<(Etot + 255) / 256, 256>>>(ei, E, Etot, N);
    scanA_kernel<<<nb, 1024>>>(N);
    scanB_kernel<<<1, 1024>>>(nb);
    scanC_kernel<<<(N + 255) / 256, 256>>>(N, Etot);
    scatter_kernel<<<(Etot + 255) / 256, 256>>>(ei, E, Etot, N);

    // layer 1
    gemm1_kernel<<<(N + 255) / 256, 256>>>(x, W1, a_src1, a_dst1, N);
    gather1_kernel<<<(N * 32 + 255) / 256, 256>>>(N);
    // layer 2
    gemm2_kernel<<<(N + 255) / 256, 256>>>(W2, a_src2, a_dst2, b1, N);
    gather2_kernel<<<(N * 32 + 255) / 256, 256>>>(b2, out, N);
}